// round 16
// baseline (speedup 1.0000x reference)
#include <cuda_runtime.h>
#include <cuda_bf16.h>
#include <cstdint>

#define T_STEPS 1024
#define F_FEAT  2048
#define MF      16
#define NCTA    (F_FEAT / MF)   // 128
#define THREADS 512

// ---- packed bf16 weight-fragment image (global, ~224 KB, L1-resident) ----
#define W1_BASE 0       // W1  (256x128): nt<32, ktp<4  -> 4096 uint4
#define W2_BASE 4096    // W2  (128x256): nt<16, ktp<8  -> 4096
#define WH_BASE 8192    // Whh (384x128): nt<48, ktp<4  -> 6144
__device__ __align__(16) uint4 g_Wfrag[14336];

__device__ __forceinline__ uint32_t bfbits(__nv_bfloat162 v) {
    return *reinterpret_cast<uint32_t*>(&v);
}

__global__ void repack_kernel(const float* __restrict__ W1,
                              const float* __restrict__ W2,
                              const float* __restrict__ Whh)
{
    int i = blockIdx.x * blockDim.x + threadIdx.x;
    if (i >= 14336) return;
    const float* W; int NK, r;
    if (i < 4096)      { W = W1;  NK = 128; r = i; }
    else if (i < 8192) { W = W2;  NK = 256; r = i - 4096; }
    else               { W = Whh; NK = 128; r = i - 8192; }
    const int NKTP = NK / 32;
    const int nt   = r / (NKTP * 32);
    const int ktp  = (r / 32) % NKTP;
    const int lane = r & 31;
    const int j  = nt * 8 + (lane >> 2);
    const int k0 = ktp * 32 + (lane & 3) * 2;
    const float* row = W + (long)j * NK;
    uint4 v;
    v.x = bfbits(__floats2bfloat162_rn(row[k0],      row[k0 + 1]));
    v.y = bfbits(__floats2bfloat162_rn(row[k0 + 8],  row[k0 + 9]));
    v.z = bfbits(__floats2bfloat162_rn(row[k0 + 16], row[k0 + 17]));
    v.w = bfbits(__floats2bfloat162_rn(row[k0 + 24], row[k0 + 25]));
    g_Wfrag[i] = v;
}

// ---- helpers ----
__device__ __forceinline__ void mma4(float* c, const uint4& a, uint32_t b0, uint32_t b1) {
    asm volatile("mma.sync.aligned.m16n8k16.row.col.f32.bf16.bf16.f32 "
        "{%0,%1,%2,%3}, {%4,%5,%6,%7}, {%8,%9}, {%0,%1,%2,%3};"
        : "+f"(c[0]), "+f"(c[1]), "+f"(c[2]), "+f"(c[3])
        : "r"(a.x), "r"(a.y), "r"(a.z), "r"(a.w), "r"(b0), "r"(b1));
}
__device__ __forceinline__ float tanh_fast(float x) {
    float y; asm("tanh.approx.f32 %0, %1;" : "=f"(y) : "f"(x)); return y;
}
__device__ __forceinline__ float fsig(float x) {
    return fmaf(0.5f, tanh_fast(0.5f * x), 0.5f);
}
__device__ __forceinline__ uint32_t packbf(float ev, float od) {
    uint32_t d; asm("cvt.rn.bf16x2.f32 %0, %1, %2;" : "=r"(d) : "f"(od), "f"(ev)); return d;
}
__device__ __forceinline__ float lo16f(uint32_t u) { return __uint_as_float(u << 16); }
__device__ __forceinline__ float hi16f(uint32_t u) { return __uint_as_float(u & 0xFFFF0000u); }

__device__ __forceinline__ void pack_hi(const float* v, uint4& hi) {
    hi.x = packbf(v[0], v[1]);
    hi.y = packbf(v[2], v[3]);
    hi.z = packbf(v[4], v[5]);
    hi.w = packbf(v[6], v[7]);
}

// ---- main kernel ----
__global__ void __launch_bounds__(THREADS, 1)
ode_mma_kernel(const float* __restrict__ times, const float* __restrict__ vals,
               const float* __restrict__ mask,  const float* __restrict__ b1,
               const float* __restrict__ b2,    const float* __restrict__ W_ih,
               const float* __restrict__ b_ih,  const float* __restrict__ b_hh,
               float* __restrict__ out)
{
    // hfrag: uint2-granular [kt][hi/lo][lane][half]; read as uint4 per (kt,hl,lane)
    __shared__ __align__(16) uint2 hfrag2[8 * 2 * 32 * 2];   // 8 KB
    __shared__ __align__(16) uint4 t1frag[16 * 32];          // 8 KB (hi-only)
    __shared__ float obs_s[16], m_s[16];

    const int tid = threadIdx.x, w = tid >> 5, lane = tid & 31;
    const int g = lane >> 2, t = lane & 3;
    const int f0 = blockIdx.x * MF;
    const uint4* hfrag4 = (const uint4*)hfrag2;
    const int kt_h = w >> 1, hf_h = w & 1;        // this warp's h slot

    // ---- loop-invariant per-lane preloads ----
    float b1v[4];
    #pragma unroll
    for (int nt = 0; nt < 2; ++nt) {
        const int j = 16 * w + nt * 8 + 2 * t;
        b1v[nt * 2]     = __ldg(b1 + j);
        b1v[nt * 2 + 1] = __ldg(b1 + j + 1);
    }
    const int k0 = 8 * w + 2 * t;                 // this lane's k base (P2/P3/h)
    float b2v[2], bcr[2], bcz[2], bhn[2], bin[2], wir[2], wiz[2], win[2];
    #pragma unroll
    for (int p = 0; p < 2; ++p) {
        const int k = k0 + p;
        b2v[p] = __ldg(b2 + k);
        bcr[p] = __ldg(b_hh + k)       + __ldg(b_ih + k);
        bcz[p] = __ldg(b_hh + 128 + k) + __ldg(b_ih + 128 + k);
        bhn[p] = __ldg(b_hh + 256 + k);
        bin[p] = __ldg(b_ih + 256 + k);
        wir[p] = __ldg(W_ih + k);
        wiz[p] = __ldg(W_ih + 128 + k);
        win[p] = __ldg(W_ih + 256 + k);
    }

    // h master: 4 fp32/lane: {row g k0, row g k0+1, row g+8 k0, row g+8 k0+1}
    float h[4];
    #pragma unroll
    for (int q = 0; q < 4; ++q) h[q] = 0.0f;

    // write this warp's half-k-tile of hfrag (hi + lo)
    auto store_h = [&] {
        uint2 hi, lo;
        hi.x = packbf(h[0], h[1]);
        hi.y = packbf(h[2], h[3]);
        lo.x = packbf(h[0] - lo16f(hi.x), h[1] - hi16f(hi.x));
        lo.y = packbf(h[2] - lo16f(hi.y), h[3] - hi16f(hi.y));
        hfrag2[((kt_h * 2 + 0) * 32 + lane) * 2 + hf_h] = hi;
        hfrag2[((kt_h * 2 + 1) * 32 + lane) * 2 + hf_h] = lo;
    };
    store_h();
    __syncthreads();

    for (int i = 0; i < T_STEPS; ++i) {
        const int rowi = T_STEPS - 1 - i;
        float dt = 0.0f;
        if (i > 0) dt = __ldg(times + rowi + 1) - __ldg(times + rowi);

        if (tid < 16)      obs_s[tid]    = __ldg(vals + (long)rowi * F_FEAT + f0 + tid);
        else if (tid < 32) m_s[tid - 16] = __ldg(mask + (long)rowi * F_FEAT + f0 + tid - 16);

        if (dt > 0.0f) {
            // ---- P1: C(16x256) = H_hi @ W1^T ; warp w: n-cols [16w,16w+16) ----
            float c[2][4];
            #pragma unroll
            for (int nt = 0; nt < 2; ++nt)
                #pragma unroll
                for (int cc = 0; cc < 4; ++cc) c[nt][cc] = 0.0f;
            uint4 bwA[2], bwB[2];
            #pragma unroll
            for (int nt = 0; nt < 2; ++nt)
                bwA[nt] = __ldg(&g_Wfrag[W1_BASE + (((2 * w + nt) * 4 + 0) * 32 + lane)]);
            #pragma unroll
            for (int ktp = 0; ktp < 4; ++ktp) {
                uint4* cur = (ktp & 1) ? bwB : bwA;
                uint4* nxt = (ktp & 1) ? bwA : bwB;
                if (ktp < 3) {
                    #pragma unroll
                    for (int nt = 0; nt < 2; ++nt)
                        nxt[nt] = __ldg(&g_Wfrag[W1_BASE + (((2 * w + nt) * 4 + ktp + 1) * 32 + lane)]);
                }
                const uint4 ah0 = hfrag4[((2 * ktp)     * 2 + 0) * 32 + lane];
                const uint4 ah1 = hfrag4[((2 * ktp + 1) * 2 + 0) * 32 + lane];
                #pragma unroll
                for (int nt = 0; nt < 2; ++nt) {
                    mma4(c[nt], ah0, cur[nt].x, cur[nt].y);
                    mma4(c[nt], ah1, cur[nt].z, cur[nt].w);
                }
            }
            // epilogue: tanh(+b1) -> T1 ktile w (hi-only, one full A-frag)
            float v[8];
            #pragma unroll
            for (int nt = 0; nt < 2; ++nt)
                #pragma unroll
                for (int cc = 0; cc < 4; ++cc)
                    v[nt * 4 + cc] = tanh_fast(c[nt][cc] + b1v[nt * 2 + (cc & 1)]);
            uint4 t1h;
            pack_hi(v, t1h);
            t1frag[w * 32 + lane] = t1h;
            // prefetch P2 ktp0 weights across the barrier
            uint4 dwA, dwB;
            dwA = __ldg(&g_Wfrag[W2_BASE + ((w * 8 + 0) * 32 + lane)]);
            __syncthreads();

            // ---- P2: C(16x128) = T1_hi @ W2^T ; warp w: n-cols [8w,8w+8) ----
            float d[4];
            #pragma unroll
            for (int cc = 0; cc < 4; ++cc) d[cc] = 0.0f;
            #pragma unroll
            for (int ktp = 0; ktp < 8; ++ktp) {
                uint4 cur = (ktp & 1) ? dwB : dwA;
                if (ktp < 7) {
                    uint4 nx = __ldg(&g_Wfrag[W2_BASE + ((w * 8 + ktp + 1) * 32 + lane)]);
                    if (ktp & 1) dwA = nx; else dwB = nx;
                }
                const uint4 ah0 = t1frag[(2 * ktp)     * 32 + lane];
                const uint4 ah1 = t1frag[(2 * ktp + 1) * 32 + lane];
                mma4(d, ah0, cur.x, cur.y);
                mma4(d, ah1, cur.z, cur.w);
            }
            // epilogue: h += dt * (dH + b2)
            #pragma unroll
            for (int q = 0; q < 4; ++q)
                h[q] = fmaf(dt, d[q] + b2v[q & 1], h[q]);
            store_h();
        }
        // prefetch P3 ktp0 weights across the barrier
        uint4 ewA[3], ewB[3];
        #pragma unroll
        for (int th = 0; th < 3; ++th)
            ewA[th] = __ldg(&g_Wfrag[WH_BASE + (((th * 16 + w) * 4 + 0) * 32 + lane)]);
        __syncthreads();

        // ---- P3: GH(16x384) = H(hi+lo) @ Whh^T ; warp w: cols [8w,8w+8) per third ----
        float e[3][4];
        #pragma unroll
        for (int th = 0; th < 3; ++th)
            #pragma unroll
            for (int cc = 0; cc < 4; ++cc) e[th][cc] = 0.0f;
        #pragma unroll
        for (int ktp = 0; ktp < 4; ++ktp) {
            uint4* cur = (ktp & 1) ? ewB : ewA;
            uint4* nxt = (ktp & 1) ? ewA : ewB;
            if (ktp < 3) {
                #pragma unroll
                for (int th = 0; th < 3; ++th)
                    nxt[th] = __ldg(&g_Wfrag[WH_BASE + (((th * 16 + w) * 4 + ktp + 1) * 32 + lane)]);
            }
            const uint4 ah0 = hfrag4[((2 * ktp)     * 2 + 0) * 32 + lane];
            const uint4 al0 = hfrag4[((2 * ktp)     * 2 + 1) * 32 + lane];
            const uint4 ah1 = hfrag4[((2 * ktp + 1) * 2 + 0) * 32 + lane];
            const uint4 al1 = hfrag4[((2 * ktp + 1) * 2 + 1) * 32 + lane];
            #pragma unroll
            for (int th = 0; th < 3; ++th) {
                float* acc = e[th];
                mma4(acc, ah0, cur[th].x, cur[th].y);
                mma4(acc, al0, cur[th].x, cur[th].y);
                mma4(acc, ah1, cur[th].z, cur[th].w);
                mma4(acc, al1, cur[th].z, cur[th].w);
            }
        }
        // RACE FIX: all warps must finish reading hfrag (h_t) before any store_h
        // below overwrites it with h_{t+1}.
        __syncthreads();

        // epilogue: GRU + mask mix, in-place on h regs
        {
            const float ob0 = obs_s[g], ob1 = obs_s[g + 8];
            const float mm0 = m_s[g],   mm1 = m_s[g + 8];
            #pragma unroll
            for (int q = 0; q < 4; ++q) {
                const int p = q & 1;
                const float ob = (q & 2) ? ob1 : ob0;
                const float mm = (q & 2) ? mm1 : mm0;
                const float r = fsig(fmaf(ob, wir[p], bcr[p]) + e[0][q]);
                const float z = fsig(fmaf(ob, wiz[p], bcz[p]) + e[1][q]);
                const float n = tanh_fast(fmaf(ob, win[p], bin[p]) + r * (e[2][q] + bhn[p]));
                const float hv = h[q];
                const float hc = fmaf(z, hv - n, n);
                h[q] = fmaf(mm, hc - hv, hv);
            }
        }
        store_h();
        __syncthreads();
    }

    // ---- output: decode fragment layout ----
    #pragma unroll
    for (int q = 0; q < 4; ++q) {
        const int rowf = g + (q >> 1) * 8;
        const int k    = k0 + (q & 1);
        out[(long)(f0 + rowf) * 128 + k] = h[q];
    }
}

extern "C" void kernel_launch(void* const* d_in, const int* in_sizes, int n_in,
                              void* d_out, int out_size)
{
    (void)in_sizes; (void)n_in; (void)out_size;
    const float* times = (const float*)d_in[0];
    const float* vals  = (const float*)d_in[1];
    const float* mask  = (const float*)d_in[2];
    const float* W1    = (const float*)d_in[3];
    const float* b1    = (const float*)d_in[4];
    const float* W2    = (const float*)d_in[5];
    const float* b2    = (const float*)d_in[6];
    const float* W_ih  = (const float*)d_in[7];
    const float* b_ih  = (const float*)d_in[8];
    const float* W_hh  = (const float*)d_in[9];
    const float* b_hh  = (const float*)d_in[10];
    float* out = (float*)d_out;

    repack_kernel<<<56, 256>>>(W1, W2, W_hh);
    ode_mma_kernel<<<NCTA, THREADS>>>(times, vals, mask, b1, b2,
                                      W_ih, b_ih, b_hh, out);
}

// round 17
// speedup vs baseline: 1.4844x; 1.4844x over previous
#include <cuda_runtime.h>
#include <cuda_fp16.h>
#include <cstdint>

#define T_STEPS 1024
#define F_FEAT  2048
#define MF      16
#define NCTA    (F_FEAT / MF)   // 128
#define THREADS 256

// ---- packed fp16 weight-fragment image (global, ~224 KB, L1-resident) ----
#define W1_BASE 0       // W1  (256x128): nt<32, ktp<4  -> 4096 uint4
#define W2_BASE 4096    // W2  (128x256): nt<16, ktp<8  -> 4096
#define WH_BASE 8192    // Whh (384x128): nt<48, ktp<4  -> 6144
__device__ __align__(16) uint4 g_Wfrag[14336];

__device__ __forceinline__ uint32_t h2bits(__half2 v) {
    return *reinterpret_cast<uint32_t*>(&v);
}

__global__ void repack_kernel(const float* __restrict__ W1,
                              const float* __restrict__ W2,
                              const float* __restrict__ Whh)
{
    int i = blockIdx.x * blockDim.x + threadIdx.x;
    if (i >= 14336) return;
    const float* W; int NK, r;
    if (i < 4096)      { W = W1;  NK = 128; r = i; }
    else if (i < 8192) { W = W2;  NK = 256; r = i - 4096; }
    else               { W = Whh; NK = 128; r = i - 8192; }
    const int NKTP = NK / 32;
    const int nt   = r / (NKTP * 32);
    const int ktp  = (r / 32) % NKTP;
    const int lane = r & 31;
    const int j  = nt * 8 + (lane >> 2);
    const int k0 = ktp * 32 + (lane & 3) * 2;
    const float* row = W + (long)j * NK;
    uint4 v;
    v.x = h2bits(__floats2half2_rn(row[k0],      row[k0 + 1]));
    v.y = h2bits(__floats2half2_rn(row[k0 + 8],  row[k0 + 9]));
    v.z = h2bits(__floats2half2_rn(row[k0 + 16], row[k0 + 17]));
    v.w = h2bits(__floats2half2_rn(row[k0 + 24], row[k0 + 25]));
    g_Wfrag[i] = v;
}

// ---- helpers ----
__device__ __forceinline__ void mma4(float* c, const uint4& a, uint32_t b0, uint32_t b1) {
    asm volatile("mma.sync.aligned.m16n8k16.row.col.f32.f16.f16.f32 "
        "{%0,%1,%2,%3}, {%4,%5,%6,%7}, {%8,%9}, {%0,%1,%2,%3};"
        : "+f"(c[0]), "+f"(c[1]), "+f"(c[2]), "+f"(c[3])
        : "r"(a.x), "r"(a.y), "r"(a.z), "r"(a.w), "r"(b0), "r"(b1));
}
__device__ __forceinline__ float tanh_fast(float x) {
    float y; asm("tanh.approx.f32 %0, %1;" : "=f"(y) : "f"(x)); return y;
}
__device__ __forceinline__ float fsig(float x) {
    return fmaf(0.5f, tanh_fast(0.5f * x), 0.5f);
}
// pack {low=ev, high=od} f16x2
__device__ __forceinline__ uint32_t packf16(float ev, float od) {
    uint32_t d; asm("cvt.rn.f16x2.f32 %0, %1, %2;" : "=r"(d) : "f"(od), "f"(ev)); return d;
}
__device__ __forceinline__ void pack_frag(const float* v, uint4& f) {
    f.x = packf16(v[0], v[1]);
    f.y = packf16(v[2], v[3]);
    f.z = packf16(v[4], v[5]);
    f.w = packf16(v[6], v[7]);
}

// ---- main kernel ----
__global__ void __launch_bounds__(THREADS, 1)
ode_mma_kernel(const float* __restrict__ times, const float* __restrict__ vals,
               const float* __restrict__ mask,  const float* __restrict__ b1,
               const float* __restrict__ b2,    const float* __restrict__ W_ih,
               const float* __restrict__ b_ih,  const float* __restrict__ b_hh,
               float* __restrict__ out)
{
    // single-fp16 A-fragment stores: [kt][lane]
    __shared__ __align__(16) uint4 hfrag[8 * 32];     // h  (K=128) 4 KB
    __shared__ __align__(16) uint4 t1frag[16 * 32];   // T1 (K=256) 8 KB
    __shared__ float obs_s[16], m_s[16];

    const int tid = threadIdx.x, w = tid >> 5, lane = tid & 31;
    const int g = lane >> 2, t = lane & 3;
    const int f0 = blockIdx.x * MF;

    // ---- loop-invariant per-lane preloads ----
    float b1v[8];
    #pragma unroll
    for (int nt = 0; nt < 4; ++nt) {
        const int j = 32 * w + nt * 8 + 2 * t;
        b1v[nt * 2]     = __ldg(b1 + j);
        b1v[nt * 2 + 1] = __ldg(b1 + j + 1);
    }
    float b2v[8], bcr[8], bcz[8], bhn[8], bin[8], wir[8], wiz[8], win[8];
    #pragma unroll
    for (int q = 0; q < 8; ++q) {
        const int k = 16 * w + (q >> 2) * 8 + 2 * t + (q & 1);
        b2v[q] = __ldg(b2 + k);
        bcr[q] = __ldg(b_hh + k)       + __ldg(b_ih + k);
        bcz[q] = __ldg(b_hh + 128 + k) + __ldg(b_ih + 128 + k);
        bhn[q] = __ldg(b_hh + 256 + k);
        bin[q] = __ldg(b_ih + 256 + k);
        wir[q] = __ldg(W_ih + k);
        wiz[q] = __ldg(W_ih + 128 + k);
        win[q] = __ldg(W_ih + 256 + k);
    }

    // h master: 8 fp32/lane, A-frag order; ktile w
    float h[8];
    #pragma unroll
    for (int q = 0; q < 8; ++q) h[q] = 0.0f;
    {
        uint4 f;
        pack_frag(h, f);
        hfrag[w * 32 + lane] = f;
    }
    __syncthreads();

    for (int i = 0; i < T_STEPS; ++i) {
        const int rowi = T_STEPS - 1 - i;
        float dt = 0.0f;
        if (i > 0) dt = __ldg(times + rowi + 1) - __ldg(times + rowi);

        if (tid < 16)      obs_s[tid]    = __ldg(vals + (long)rowi * F_FEAT + f0 + tid);
        else if (tid < 32) m_s[tid - 16] = __ldg(mask + (long)rowi * F_FEAT + f0 + tid - 16);

        if (dt > 0.0f) {
            // ---- P1: C(16x256) = H @ W1^T ; warp w: n-cols [32w,32w+32) ----
            float c[4][4];
            #pragma unroll
            for (int nt = 0; nt < 4; ++nt)
                #pragma unroll
                for (int cc = 0; cc < 4; ++cc) c[nt][cc] = 0.0f;
            uint4 bwA[4], bwB[4];
            #pragma unroll
            for (int nt = 0; nt < 4; ++nt)
                bwA[nt] = __ldg(&g_Wfrag[W1_BASE + (((4 * w + nt) * 4 + 0) * 32 + lane)]);
            #pragma unroll
            for (int ktp = 0; ktp < 4; ++ktp) {
                uint4* cur = (ktp & 1) ? bwB : bwA;
                uint4* nxt = (ktp & 1) ? bwA : bwB;
                if (ktp < 3) {
                    #pragma unroll
                    for (int nt = 0; nt < 4; ++nt)
                        nxt[nt] = __ldg(&g_Wfrag[W1_BASE + (((4 * w + nt) * 4 + ktp + 1) * 32 + lane)]);
                }
                const uint4 ah0 = hfrag[(2 * ktp)     * 32 + lane];
                const uint4 ah1 = hfrag[(2 * ktp + 1) * 32 + lane];
                #pragma unroll
                for (int nt = 0; nt < 4; ++nt) {
                    mma4(c[nt], ah0, cur[nt].x, cur[nt].y);
                    mma4(c[nt], ah1, cur[nt].z, cur[nt].w);
                }
            }
            // epilogue: tanh(+b1) -> T1 A-frags (ktiles 2w, 2w+1)
            float v[16];
            #pragma unroll
            for (int nt = 0; nt < 4; ++nt)
                #pragma unroll
                for (int cc = 0; cc < 4; ++cc)
                    v[nt * 4 + cc] = tanh_fast(c[nt][cc] + b1v[nt * 2 + (cc & 1)]);
            #pragma unroll
            for (int kt2 = 0; kt2 < 2; ++kt2) {
                uint4 f;
                pack_frag(v + kt2 * 8, f);
                t1frag[(2 * w + kt2) * 32 + lane] = f;
            }
            // prefetch P2 ktp0 weights across the barrier
            uint4 dwA[2], dwB[2];
            #pragma unroll
            for (int nt = 0; nt < 2; ++nt)
                dwA[nt] = __ldg(&g_Wfrag[W2_BASE + (((2 * w + nt) * 8 + 0) * 32 + lane)]);
            __syncthreads();

            // ---- P2: C(16x128) = T1 @ W2^T ; warp w: n-cols [16w,16w+16) ----
            float d[2][4];
            #pragma unroll
            for (int nt = 0; nt < 2; ++nt)
                #pragma unroll
                for (int cc = 0; cc < 4; ++cc) d[nt][cc] = 0.0f;
            #pragma unroll
            for (int ktp = 0; ktp < 8; ++ktp) {
                uint4* cur = (ktp & 1) ? dwB : dwA;
                uint4* nxt = (ktp & 1) ? dwA : dwB;
                if (ktp < 7) {
                    #pragma unroll
                    for (int nt = 0; nt < 2; ++nt)
                        nxt[nt] = __ldg(&g_Wfrag[W2_BASE + (((2 * w + nt) * 8 + ktp + 1) * 32 + lane)]);
                }
                const uint4 ah0 = t1frag[(2 * ktp)     * 32 + lane];
                const uint4 ah1 = t1frag[(2 * ktp + 1) * 32 + lane];
                #pragma unroll
                for (int nt = 0; nt < 2; ++nt) {
                    mma4(d[nt], ah0, cur[nt].x, cur[nt].y);
                    mma4(d[nt], ah1, cur[nt].z, cur[nt].w);
                }
            }
            // epilogue: h += dt * (dH + b2); refresh h frag
            #pragma unroll
            for (int q = 0; q < 8; ++q)
                h[q] = fmaf(dt, d[q >> 2][q & 3] + b2v[q], h[q]);
            {
                uint4 f;
                pack_frag(h, f);
                hfrag[w * 32 + lane] = f;
            }
        }
        // prefetch P3 ktp0 weights across the barrier
        uint4 ewA[6], ewB[6];
        #pragma unroll
        for (int j6 = 0; j6 < 6; ++j6)
            ewA[j6] = __ldg(&g_Wfrag[WH_BASE + ((((j6 >> 1) * 16 + 2 * w + (j6 & 1)) * 4 + 0) * 32 + lane)]);
        __syncthreads();

        // ---- P3: GH(16x384) = H @ Whh^T ; warp w: cols 16w..16w+16 per third ----
        float e[6][4];
        #pragma unroll
        for (int nt = 0; nt < 6; ++nt)
            #pragma unroll
            for (int cc = 0; cc < 4; ++cc) e[nt][cc] = 0.0f;
        #pragma unroll
        for (int ktp = 0; ktp < 4; ++ktp) {
            uint4* cur = (ktp & 1) ? ewB : ewA;
            uint4* nxt = (ktp & 1) ? ewA : ewB;
            if (ktp < 3) {
                #pragma unroll
                for (int j6 = 0; j6 < 6; ++j6)
                    nxt[j6] = __ldg(&g_Wfrag[WH_BASE + ((((j6 >> 1) * 16 + 2 * w + (j6 & 1)) * 4 + ktp + 1) * 32 + lane)]);
            }
            const uint4 ah0 = hfrag[(2 * ktp)     * 32 + lane];
            const uint4 ah1 = hfrag[(2 * ktp + 1) * 32 + lane];
            #pragma unroll
            for (int j6 = 0; j6 < 6; ++j6) {
                float* acc = e[j6];
                mma4(acc, ah0, cur[j6].x, cur[j6].y);
                mma4(acc, ah1, cur[j6].z, cur[j6].w);
            }
        }
        // RACE FIX: all warps must finish reading hfrag (h_t) before the
        // epilogue below overwrites it with h_{t+1}.
        __syncthreads();

        // epilogue: GRU + mask mix, in-place on h regs (C layout == h layout)
        {
            const float ob0 = obs_s[g], ob1 = obs_s[g + 8];
            const float mm0 = m_s[g],   mm1 = m_s[g + 8];
            #pragma unroll
            for (int q = 0; q < 8; ++q) {
                const int tile = q >> 2, cc = q & 3;
                const float ob = (cc & 2) ? ob1 : ob0;
                const float mm = (cc & 2) ? mm1 : mm0;
                const float r = fsig(fmaf(ob, wir[q], bcr[q]) + e[tile][cc]);
                const float z = fsig(fmaf(ob, wiz[q], bcz[q]) + e[2 + tile][cc]);
                const float n = tanh_fast(fmaf(ob, win[q], bin[q]) + r * (e[4 + tile][cc] + bhn[q]));
                const float hv = h[q];
                const float hc = fmaf(z, hv - n, n);
                h[q] = fmaf(mm, hc - hv, hv);
            }
        }
        {
            uint4 f;
            pack_frag(h, f);
            hfrag[w * 32 + lane] = f;
        }
        __syncthreads();
    }

    // ---- output: decode fragment layout ----
    #pragma unroll
    for (int q = 0; q < 8; ++q) {
        const int rowf = g + ((q & 3) >> 1) * 8;
        const int k    = 16 * w + (q >> 2) * 8 + 2 * t + (q & 1);
        out[(long)(f0 + rowf) * 128 + k] = h[q];
    }
}

extern "C" void kernel_launch(void* const* d_in, const int* in_sizes, int n_in,
                              void* d_out, int out_size)
{
    (void)in_sizes; (void)n_in; (void)out_size;
    const float* times = (const float*)d_in[0];
    const float* vals  = (const float*)d_in[1];
    const float* mask  = (const float*)d_in[2];
    const float* W1    = (const float*)d_in[3];
    const float* b1    = (const float*)d_in[4];
    const float* W2    = (const float*)d_in[5];
    const float* b2    = (const float*)d_in[6];
    const float* W_ih  = (const float*)d_in[7];
    const float* b_ih  = (const float*)d_in[8];
    const float* W_hh  = (const float*)d_in[9];
    const float* b_hh  = (const float*)d_in[10];
    float* out = (float*)d_out;

    repack_kernel<<<56, 256>>>(W1, W2, W_hh);
    ode_mma_kernel<<<NCTA, THREADS>>>(times, vals, mask, b1, b2,
                                      W_ih, b_ih, b_hh, out);
}